// round 16
// baseline (speedup 1.0000x reference)
#include <cuda_runtime.h>
#include <cstdint>

typedef unsigned int u32;

static constexpr int D = 1024;
static constexpr int K = 32;
static constexpr int NT = 256;       // 8 warps
static constexpr int TILE_R = 128;   // rows per block
static constexpr int DC = 32;        // d per chunk
static constexpr int NCH = D / DC;   // 32

// smem float offsets (V stride 40 -> conflict-free LDS.64 fragment loads)
static constexpr int VB0 = 0;        // 32*40 = 1280
static constexpr int VB1 = 1280;
static constexpr int PO  = 2560;     // P: 128*33 = 4224
static constexpr int SCO = 6784;     // C: 1024
static constexpr int SM_FLOATS = 7808;    // 31232 B

__device__ float g_G[K * K];
__device__ float g_C[K * K];
__device__ float g_Vt[D * K];        // Vt[d][k]

__device__ __forceinline__ void mma8(float* d, u32 a0, u32 a1, u32 a2, u32 a3,
                                     u32 b0, u32 b1) {
    asm volatile("mma.sync.aligned.m16n8k8.row.col.f32.tf32.tf32.f32 "
        "{%0,%1,%2,%3}, {%4,%5,%6,%7}, {%8,%9}, {%0,%1,%2,%3};"
        : "+f"(d[0]), "+f"(d[1]), "+f"(d[2]), "+f"(d[3])
        : "r"(a0), "r"(a1), "r"(a2), "r"(a3), "r"(b0), "r"(b1));
}
__device__ __forceinline__ void cp16(float* s, const float* g) {
    u32 ss = (u32)__cvta_generic_to_shared(s);
    asm volatile("cp.async.cg.shared.global [%0], [%1], 16;" :: "r"(ss), "l"(g) : "memory");
}
#define CP_COMMIT() asm volatile("cp.async.commit_group;" ::: "memory")
#define CP_WAIT1()  asm volatile("cp.async.wait_group 1;" ::: "memory")
#define CP_WAIT0()  asm volatile("cp.async.wait_group 0;" ::: "memory")
#define F2U(x) __float_as_uint(x)

// ---------------- G = V V^T + build g_Vt ----------------
__global__ void gram_kernel(const float* __restrict__ V) {
    int k1 = blockIdx.x;
    int w = threadIdx.x >> 5;
    int lane = threadIdx.x & 31;
    #pragma unroll
    for (int i = 0; i < 4; i++) {
        int k2 = w * 4 + i;
        float s = 0.f;
        #pragma unroll
        for (int j = 0; j < D; j += 128) {
            float4 a = *(const float4*)(V + k1 * D + j + lane * 4);
            float4 b = *(const float4*)(V + k2 * D + j + lane * 4);
            s += a.x * b.x + a.y * b.y + a.z * b.z + a.w * b.w;
        }
        #pragma unroll
        for (int o = 16; o; o >>= 1) s += __shfl_down_sync(0xffffffffu, s, o);
        if (lane == 0) g_G[k1 * K + k2] = s;
    }
    for (int d = threadIdx.x; d < D; d += 256)
        g_Vt[d * K + k1] = V[k1 * D + d];
}

// ---------------- C = (I+U)^{-1} diag(beta) ----------------
__global__ void prepc_kernel() {
    __shared__ float G[K * K];
    __shared__ float beta[K];
    int t = threadIdx.x;
    for (int i = t; i < K * K; i += 32) G[i] = g_G[i];
    __syncwarp();
    beta[t] = 1.f / G[t * K + t];
    __syncwarp();
    float x[K];
    int c = t;
    for (int j = 0; j < K; j++) x[j] = 0.f;
    x[c] = 1.f;
    for (int j = c - 1; j >= 0; j--) {
        float s = 0.f;
        for (int m = j + 1; m <= c; m++) s += beta[j] * G[j * K + m] * x[m];
        x[j] = -s;
    }
    for (int j = 0; j < K; j++) g_C[j * K + c] = x[j] * beta[c];
}

// ---------------- fused: out = h - ((h V^T) C) V, tf32 mma.sync ----------------
__global__ __launch_bounds__(NT, 3) void fused_kernel(
    const float* __restrict__ H, const float* __restrict__ V,
    float* __restrict__ OUT)
{
    extern __shared__ __align__(16) float sm[];

    const int t = threadIdx.x;
    const int wid = t >> 5;
    const int lid = t & 31;
    const int g = lid >> 2;
    const int tq = lid & 3;
    const int w16 = wid * 16;
    const int row0 = blockIdx.x * TILE_R;

    float* sC = sm + SCO;
    for (int i = t; i < K * K; i += NT) sC[i] = g_C[i];

    const int fc = t & 7;
    const int sr = t >> 3;           // 0..31

    // this thread's two H rows (fragment rows)
    const float* hrow0 = H + (size_t)(row0 + w16 + g) * D;
    const float* hrow1 = hrow0 + (size_t)8 * D;
    float* orow0 = OUT + (size_t)(row0 + w16 + g) * D;
    float* orow1 = orow0 + (size_t)8 * D;

    auto loadHfrag = [&](int c, float2* ha) {  // 8 x LDG.64.CS, streaming
        const float* b0 = hrow0 + c * DC + 2 * tq;
        const float* b1 = hrow1 + c * DC + 2 * tq;
        #pragma unroll
        for (int ks = 0; ks < 4; ks++) {
            ha[ks * 2 + 0] = __ldcs((const float2*)(b0 + ks * 8));
            ha[ks * 2 + 1] = __ldcs((const float2*)(b1 + ks * 8));
        }
    };
    auto stageVs = [&](int c, int b) {     // V natural [k][d], stride 40 (phase A)
        float* dst = sm + (b ? VB1 : VB0);
        cp16(dst + sr * 40 + fc * 4, V + (size_t)sr * D + c * DC + fc * 4);
    };
    auto stageVt = [&](int c, int b) {     // Vt [d][k], stride 40 (phase B)
        float* dst = sm + (b ? VB1 : VB0);
        cp16(dst + sr * 40 + fc * 4, g_Vt + (size_t)(c * DC + sr) * K + fc * 4);
    };

    // ============ Phase A: P = H V^T (contraction over d, permuted) ============
    float pacc[4][4];
    #pragma unroll
    for (int nt = 0; nt < 4; nt++)
        #pragma unroll
        for (int i = 0; i < 4; i++) pacc[nt][i] = 0.f;

    float2 ha[2][8];
    stageVs(0, 0); CP_COMMIT();
    loadHfrag(0, ha[0]);
    for (int c = 0; c < NCH; c++) {
        int b = c & 1;
        if (c + 1 < NCH) {
            stageVs(c + 1, b ^ 1); CP_COMMIT();
            loadHfrag(c + 1, ha[b ^ 1]);     // register prefetch, MLP=8
            CP_WAIT1();
        } else CP_WAIT0();
        __syncthreads();
        const float* vs = sm + (b ? VB1 : VB0);
        #pragma unroll
        for (int ks = 0; ks < 4; ks++) {
            int d0 = ks * 8 + 2 * tq;
            float2 av0 = ha[b][ks * 2 + 0];
            float2 av1 = ha[b][ks * 2 + 1];
            #pragma unroll
            for (int nt = 0; nt < 4; nt++) {
                float2 bv = *(const float2*)(&vs[(nt * 8 + g) * 40 + d0]);
                mma8(pacc[nt], F2U(av0.x), F2U(av1.x), F2U(av0.y), F2U(av1.y),
                     F2U(bv.x), F2U(bv.y));
            }
        }
        __syncthreads();
    }

    // ---- P -> PO (stride 33) ----
    {
        float* P = sm + PO;
        #pragma unroll
        for (int nt = 0; nt < 4; nt++) {
            int cc = nt * 8 + 2 * tq;
            P[(w16 + g) * 33 + cc] = pacc[nt][0];
            P[(w16 + g) * 33 + cc + 1] = pacc[nt][1];
            P[(w16 + g + 8) * 33 + cc] = pacc[nt][2];
            P[(w16 + g + 8) * 33 + cc + 1] = pacc[nt][3];
        }
    }
    __syncthreads();

    // prefetch phase-B chunk 0 (V tile + H fragments)
    stageVt(0, 0); CP_COMMIT();
    loadHfrag(0, ha[0]);

    // ---- W fragments per-thread: W[r][k] = sum_j P[r][j] C[j][k] ----
    u32 wa[4][4];
    {
        const float* P = sm + PO;
        float w0[8], w1[8];
        #pragma unroll
        for (int i = 0; i < 8; i++) { w0[i] = 0.f; w1[i] = 0.f; }
        #pragma unroll 4
        for (int j = 0; j < K; j++) {
            float p0 = P[(w16 + g) * 33 + j];
            float p1 = P[(w16 + g + 8) * 33 + j];
            #pragma unroll
            for (int ks = 0; ks < 4; ks++) {
                float2 cv = *(const float2*)(&sC[j * K + ks * 8 + 2 * tq]);
                w0[ks * 2 + 0] += p0 * cv.x;
                w0[ks * 2 + 1] += p0 * cv.y;
                w1[ks * 2 + 0] += p1 * cv.x;
                w1[ks * 2 + 1] += p1 * cv.y;
            }
        }
        #pragma unroll
        for (int ks = 0; ks < 4; ks++) {
            wa[ks][0] = F2U(w0[ks * 2 + 0]);
            wa[ks][1] = F2U(w1[ks * 2 + 0]);
            wa[ks][2] = F2U(w0[ks * 2 + 1]);
            wa[ks][3] = F2U(w1[ks * 2 + 1]);
        }
    }

    // ============ Phase B: out = H - W V (H fragments direct, reg-prefetched) ====
    for (int c = 0; c < NCH; c++) {
        int b = c & 1;
        if (c + 1 < NCH) {
            stageVt(c + 1, b ^ 1); CP_COMMIT();
            loadHfrag(c + 1, ha[b ^ 1]);
            CP_WAIT1();
        } else CP_WAIT0();
        __syncthreads();
        const float* vt = sm + (b ? VB1 : VB0);
        const int dc = c * DC;
        #pragma unroll
        for (int nt = 0; nt < 4; nt++) {
            float acc[4] = {0.f, 0.f, 0.f, 0.f};
            #pragma unroll
            for (int ks = 0; ks < 4; ks++) {
                int k0 = ks * 8 + 2 * tq;
                float2 bv = *(const float2*)(&vt[(nt * 8 + g) * 40 + k0]);
                mma8(acc, wa[ks][0], wa[ks][1], wa[ks][2], wa[ks][3],
                     F2U(bv.x), F2U(bv.y));
            }
            float2 h0 = ha[b][nt * 2 + 0];
            float2 h1 = ha[b][nt * 2 + 1];
            float2 o0 = {h0.x - acc[0], h0.y - acc[1]};
            float2 o1 = {h1.x - acc[2], h1.y - acc[3]};
            *(float2*)(orow0 + dc + nt * 8 + 2 * tq) = o0;
            *(float2*)(orow1 + dc + nt * 8 + 2 * tq) = o1;
        }
        __syncthreads();
    }
}

extern "C" void kernel_launch(void* const* d_in, const int* in_sizes, int n_in,
                              void* d_out, int out_size) {
    const float* H = (const float*)d_in[0];
    const float* V = (const float*)d_in[1];
    float* OUT = (float*)d_out;
    const int N = in_sizes[0] / D;

    cudaFuncSetAttribute(fused_kernel, cudaFuncAttributeMaxDynamicSharedMemorySize,
                         SM_FLOATS * 4);
    gram_kernel<<<K, 256>>>(V);
    prepc_kernel<<<1, 32>>>();
    fused_kernel<<<N / TILE_R, NT, SM_FLOATS * 4>>>(H, V, OUT);
}

// round 17
// speedup vs baseline: 1.7414x; 1.7414x over previous
#include <cuda_runtime.h>
#include <cstdint>

typedef unsigned int u32;

static constexpr int D = 1024;
static constexpr int K = 32;
static constexpr int NT = 256;       // 8 warps
static constexpr int TILE_R = 128;   // rows per block
static constexpr int DC = 32;        // d per chunk
static constexpr int NCH = D / DC;   // 32

// smem float offsets (stride 40 -> conflict-free LDS.64 fragment loads)
static constexpr int HS0 = 0;        // 128*40 = 5120
static constexpr int HS1 = 5120;
static constexpr int VB0 = 10240;    // 32*40 = 1280
static constexpr int VB1 = 11520;
static constexpr int PO  = 12800;    // P: 128*33 = 4224
static constexpr int SCO = 17024;    // C: 1024
static constexpr int SM_FLOATS = 18048;   // 72192 B -> 3 blocks/SM

__device__ float g_G[K * K];
__device__ float g_C[K * K];
__device__ float g_Vt[D * K];        // Vt[d][k]

__device__ __forceinline__ void mma8(float* d, u32 a0, u32 a1, u32 a2, u32 a3,
                                     u32 b0, u32 b1) {
    asm volatile("mma.sync.aligned.m16n8k8.row.col.f32.tf32.tf32.f32 "
        "{%0,%1,%2,%3}, {%4,%5,%6,%7}, {%8,%9}, {%0,%1,%2,%3};"
        : "+f"(d[0]), "+f"(d[1]), "+f"(d[2]), "+f"(d[3])
        : "r"(a0), "r"(a1), "r"(a2), "r"(a3), "r"(b0), "r"(b1));
}
__device__ __forceinline__ void cp16(float* s, const float* g) {
    u32 ss = (u32)__cvta_generic_to_shared(s);
    asm volatile("cp.async.cg.shared.global [%0], [%1], 16;" :: "r"(ss), "l"(g) : "memory");
}
#define CP_COMMIT() asm volatile("cp.async.commit_group;" ::: "memory")
#define CP_WAIT1()  asm volatile("cp.async.wait_group 1;" ::: "memory")
#define CP_WAIT0()  asm volatile("cp.async.wait_group 0;" ::: "memory")
#define F2U(x) __float_as_uint(x)

// ---------------- G = V V^T + build g_Vt ----------------
__global__ void gram_kernel(const float* __restrict__ V) {
    int k1 = blockIdx.x;
    int w = threadIdx.x >> 5;
    int lane = threadIdx.x & 31;
    #pragma unroll
    for (int i = 0; i < 4; i++) {
        int k2 = w * 4 + i;
        float s = 0.f;
        #pragma unroll
        for (int j = 0; j < D; j += 128) {
            float4 a = *(const float4*)(V + k1 * D + j + lane * 4);
            float4 b = *(const float4*)(V + k2 * D + j + lane * 4);
            s += a.x * b.x + a.y * b.y + a.z * b.z + a.w * b.w;
        }
        #pragma unroll
        for (int o = 16; o; o >>= 1) s += __shfl_down_sync(0xffffffffu, s, o);
        if (lane == 0) g_G[k1 * K + k2] = s;
    }
    for (int d = threadIdx.x; d < D; d += 256)
        g_Vt[d * K + k1] = V[k1 * D + d];
}

// ---------------- C = (I+U)^{-1} diag(beta) ----------------
__global__ void prepc_kernel() {
    __shared__ float G[K * K];
    __shared__ float beta[K];
    int t = threadIdx.x;
    for (int i = t; i < K * K; i += 32) G[i] = g_G[i];
    __syncwarp();
    beta[t] = 1.f / G[t * K + t];
    __syncwarp();
    float x[K];
    int c = t;
    for (int j = 0; j < K; j++) x[j] = 0.f;
    x[c] = 1.f;
    for (int j = c - 1; j >= 0; j--) {
        float s = 0.f;
        for (int m = j + 1; m <= c; m++) s += beta[j] * G[j * K + m] * x[m];
        x[j] = -s;
    }
    for (int j = 0; j < K; j++) g_C[j * K + c] = x[j] * beta[c];
}

// ---------------- fused: out = h - ((h V^T) C) V, tf32 mma.sync ----------------
__global__ __launch_bounds__(NT, 3) void fused_kernel(
    const float* __restrict__ H, const float* __restrict__ V,
    float* __restrict__ OUT)
{
    extern __shared__ __align__(16) float sm[];

    const int t = threadIdx.x;
    const int wid = t >> 5;
    const int lid = t & 31;
    const int g = lid >> 2;
    const int tq = lid & 3;
    const int w16 = wid * 16;
    const int row0 = blockIdx.x * TILE_R;

    float* sC = sm + SCO;
    for (int i = t; i < K * K; i += NT) sC[i] = g_C[i];

    const int fc = t & 7;
    const int sr = t >> 3;           // 0..31

    auto stageH = [&](int c, int b) {      // H tile 128x32, stride 40 (coalesced)
        float* dst = sm + (b ? HS1 : HS0);
        int dc = c * DC;
        #pragma unroll
        for (int i = 0; i < 4; i++) {
            int seg = i * 256 + t, r = seg >> 3, c16 = seg & 7;
            cp16(dst + r * 40 + c16 * 4, H + (size_t)(row0 + r) * D + dc + c16 * 4);
        }
    };
    auto stageVs = [&](int c, int b) {     // V natural [k][d], stride 40 (phase A)
        float* dst = sm + (b ? VB1 : VB0);
        cp16(dst + sr * 40 + fc * 4, V + (size_t)sr * D + c * DC + fc * 4);
    };
    auto stageVt = [&](int c, int b) {     // Vt [d][k], stride 40 (phase B)
        float* dst = sm + (b ? VB1 : VB0);
        cp16(dst + sr * 40 + fc * 4, g_Vt + (size_t)(c * DC + sr) * K + fc * 4);
    };

    // ============ Phase A: P = H V^T (contraction over d, permuted) ============
    float pacc[4][4];
    #pragma unroll
    for (int nt = 0; nt < 4; nt++)
        #pragma unroll
        for (int i = 0; i < 4; i++) pacc[nt][i] = 0.f;

    stageH(0, 0); stageVs(0, 0); CP_COMMIT();
    for (int c = 0; c < NCH; c++) {
        int b = c & 1;
        if (c + 1 < NCH) {
            stageH(c + 1, b ^ 1); stageVs(c + 1, b ^ 1);
            CP_COMMIT(); CP_WAIT1();
        } else CP_WAIT0();
        __syncthreads();
        const float* hs = sm + (b ? HS1 : HS0);
        const float* vs = sm + (b ? VB1 : VB0);
        #pragma unroll
        for (int ks = 0; ks < 4; ks++) {
            int d0 = ks * 8 + 2 * tq;    // kk=tq -> d0, kk=tq+4 -> d0+1
            float2 av0 = *(const float2*)(&hs[(w16 + g) * 40 + d0]);
            float2 av1 = *(const float2*)(&hs[(w16 + g + 8) * 40 + d0]);
            #pragma unroll
            for (int nt = 0; nt < 4; nt++) {
                float2 bv = *(const float2*)(&vs[(nt * 8 + g) * 40 + d0]);
                mma8(pacc[nt], F2U(av0.x), F2U(av1.x), F2U(av0.y), F2U(av1.y),
                     F2U(bv.x), F2U(bv.y));
            }
        }
        __syncthreads();
    }

    // ---- P -> PO (stride 33) ----
    {
        float* P = sm + PO;
        #pragma unroll
        for (int nt = 0; nt < 4; nt++) {
            int cc = nt * 8 + 2 * tq;
            P[(w16 + g) * 33 + cc] = pacc[nt][0];
            P[(w16 + g) * 33 + cc + 1] = pacc[nt][1];
            P[(w16 + g + 8) * 33 + cc] = pacc[nt][2];
            P[(w16 + g + 8) * 33 + cc + 1] = pacc[nt][3];
        }
    }
    __syncthreads();

    // prefetch phase-B FIRST chunk = NCH-1 (most recently read by phase A -> L2-hot)
    stageH(NCH - 1, 0); stageVt(NCH - 1, 0); CP_COMMIT();

    // ---- W fragments per-thread: W[r][k] = sum_j P[r][j] C[j][k] ----
    u32 wa[4][4];
    {
        const float* P = sm + PO;
        float w0[8], w1[8];
        #pragma unroll
        for (int i = 0; i < 8; i++) { w0[i] = 0.f; w1[i] = 0.f; }
        #pragma unroll 4
        for (int j = 0; j < K; j++) {
            float p0 = P[(w16 + g) * 33 + j];
            float p1 = P[(w16 + g + 8) * 33 + j];
            #pragma unroll
            for (int ks = 0; ks < 4; ks++) {
                float2 cv = *(const float2*)(&sC[j * K + ks * 8 + 2 * tq]);
                w0[ks * 2 + 0] += p0 * cv.x;
                w0[ks * 2 + 1] += p0 * cv.y;
                w1[ks * 2 + 0] += p1 * cv.x;
                w1[ks * 2 + 1] += p1 * cv.y;
            }
        }
        #pragma unroll
        for (int ks = 0; ks < 4; ks++) {
            wa[ks][0] = F2U(w0[ks * 2 + 0]);
            wa[ks][1] = F2U(w1[ks * 2 + 0]);
            wa[ks][2] = F2U(w0[ks * 2 + 1]);
            wa[ks][3] = F2U(w1[ks * 2 + 1]);
        }
    }

    // ============ Phase B (REVERSED chunk order, LIFO L2 reuse): out = Hs - W V ===
    for (int i = 0; i < NCH; i++) {
        const int c = NCH - 1 - i;       // 31, 30, ..., 0
        const int b = i & 1;
        if (i + 1 < NCH) {
            stageH(c - 1, b ^ 1); stageVt(c - 1, b ^ 1);
            CP_COMMIT(); CP_WAIT1();
        } else CP_WAIT0();
        __syncthreads();
        const float* hs = sm + (b ? HS1 : HS0);
        const float* vt = sm + (b ? VB1 : VB0);
        const int dc = c * DC;
        #pragma unroll
        for (int nt = 0; nt < 4; nt++) {
            float acc[4] = {0.f, 0.f, 0.f, 0.f};
            #pragma unroll
            for (int ks = 0; ks < 4; ks++) {
                int k0 = ks * 8 + 2 * tq;
                float2 bv = *(const float2*)(&vt[(nt * 8 + g) * 40 + k0]);
                mma8(acc, wa[ks][0], wa[ks][1], wa[ks][2], wa[ks][3],
                     F2U(bv.x), F2U(bv.y));
            }
            int cc = nt * 8 + 2 * tq;
            float2 h0 = *(const float2*)(&hs[(w16 + g) * 40 + cc]);
            float2 h1 = *(const float2*)(&hs[(w16 + g + 8) * 40 + cc]);
            float2 o0 = {h0.x - acc[0], h0.y - acc[1]};
            float2 o1 = {h1.x - acc[2], h1.y - acc[3]};
            __stcs((float2*)(OUT + (size_t)(row0 + w16 + g) * D + dc + cc), o0);
            __stcs((float2*)(OUT + (size_t)(row0 + w16 + g + 8) * D + dc + cc), o1);
        }
        __syncthreads();
    }
}

extern "C" void kernel_launch(void* const* d_in, const int* in_sizes, int n_in,
                              void* d_out, int out_size) {
    const float* H = (const float*)d_in[0];
    const float* V = (const float*)d_in[1];
    float* OUT = (float*)d_out;
    const int N = in_sizes[0] / D;

    cudaFuncSetAttribute(fused_kernel, cudaFuncAttributeMaxDynamicSharedMemorySize,
                         SM_FLOATS * 4);
    gram_kernel<<<K, 256>>>(V);
    prepc_kernel<<<1, 32>>>();
    fused_kernel<<<N / TILE_R, NT, SM_FLOATS * 4>>>(H, V, OUT);
}